// round 6
// baseline (speedup 1.0000x reference)
#include <cuda_runtime.h>
#include <cuda_bf16.h>
#include <math.h>

// ---------------------------------------------------------------------------
// GCN2 (GCNII) forward:  N=100000 nodes, E=1e6 edges, IN=128, HID=64, OUT=64, L=4
//
// Pipeline (all fp32, graph-capturable, no allocations):
//   deg  = segment_sum(ones, row);  dinv = deg>0 ? rsqrt(deg) : 0
//   ew_e = dinv[row_e] * dinv[col_e]
//   x = relu(X @ W0 + b0); x0 = x; agg = (a/(1-a)) * x0
//   for i in 0..3:
//     agg += scatter_add(x[col]*ew -> row)            (SPMM, vector RED atomics)
//     s = (1-a)*agg                                    ( == (1-a)*PX + a*x0 )
//     h = (1-b)*s + b*(s @ Wc_i)   + accumulate BN sums
//     x = relu( BN(h)*gamma+beta + x );  agg = (a/(1-a))*x0   (for next layer)
//   out = x @ W1 + b1
// ---------------------------------------------------------------------------

#define Nn   100000
#define Ee   1000000
#define HID  64
#define ALPHA 0.1f
#define C0   (ALPHA / (1.0f - ALPHA))   // 0.111111...
#define BN_EPS 1e-5f

// ---- scratch (device globals; allocation-free) ----
__device__ float g_x  [Nn * HID];
__device__ float g_x0 [Nn * HID];
__device__ float g_agg[Nn * HID];
__device__ float g_h  [Nn * HID];
__device__ float g_ew [Ee];
__device__ float g_deg[Nn];
__device__ float g_bnsum[HID];
__device__ float g_bnsq [HID];

// ---------------------------------------------------------------------------
// degree / edge-weight prep
// ---------------------------------------------------------------------------
__global__ void k_zero_deg() {
    int i = blockIdx.x * blockDim.x + threadIdx.x;
    if (i < Nn) g_deg[i] = 0.0f;
}

__global__ void k_deg(const int* __restrict__ ei) {
    int e = blockIdx.x * blockDim.x + threadIdx.x;
    if (e < Ee) atomicAdd(&g_deg[ei[e]], 1.0f);
}

__device__ __forceinline__ float dinv_of(float d) {
    return d > 0.0f ? rsqrtf(d) : 0.0f;
}

__global__ void k_ew(const int* __restrict__ ei) {
    int e = blockIdx.x * blockDim.x + threadIdx.x;
    if (e < Ee) {
        float dr = dinv_of(g_deg[ei[e]]);
        float dc = dinv_of(g_deg[ei[Ee + e]]);
        g_ew[e] = dr * dc;
    }
}

// ---------------------------------------------------------------------------
// SPMM: agg[row] += x[col] * ew   (16 lanes per edge, float4 per lane,
//                                  vector RED atomics -> coalesced 256B groups)
// Also zeroes the BN accumulators for the upcoming GEMM+BN kernel.
// ---------------------------------------------------------------------------
__global__ void k_spmm(const int* __restrict__ ei) {
    if (blockIdx.x == 0 && threadIdx.x < HID) {
        g_bnsum[threadIdx.x] = 0.0f;
        g_bnsq [threadIdx.x] = 0.0f;
    }
    int t = blockIdx.x * 256 + threadIdx.x;   // grid sized exactly Ee*16
    int e = t >> 4;
    int q = t & 15;
    int row = __ldg(&ei[e]);
    int col = __ldg(&ei[Ee + e]);
    float w = g_ew[e];
    const float4 v = *(const float4*)&g_x[col * HID + q * 4];
    float4 r;
    r.x = v.x * w; r.y = v.y * w; r.z = v.z * w; r.w = v.w * w;
    float* p = &g_agg[row * HID + q * 4];
    asm volatile("red.global.add.v4.f32 [%0], {%1, %2, %3, %4};"
                 :: "l"(p), "f"(r.x), "f"(r.y), "f"(r.z), "f"(r.w)
                 : "memory");
}

// ---------------------------------------------------------------------------
// Tiled fp32 GEMM machinery: block = 256 threads, 128 rows/block,
// thread tile = 8 rows x 4 cols, k unrolled by 4 (all LDS.128).
// ---------------------------------------------------------------------------
__device__ __forceinline__ void fma4(float4& a, float s, const float4& b) {
    a.x = fmaf(s, b.x, a.x);
    a.y = fmaf(s, b.y, a.y);
    a.z = fmaf(s, b.z, a.z);
    a.w = fmaf(s, b.w, a.w);
}

// --- layer 0: x = relu(X@W0 + b0); x0 = x; agg = C0*x  (K = 128) -----------
__global__ void k_mlp0(const float* __restrict__ X,
                       const float* __restrict__ W0,
                       const float* __restrict__ b0) {
    extern __shared__ float sm[];
    float* ssh = sm;                 // 128 rows x 132 (padded)
    float* wsh = sm + 128 * 132;     // 128 x 64
    const int tid  = threadIdx.x;
    const int row0 = blockIdx.x * 128;

    for (int i = tid; i < 2048; i += 256)         // W0: 128*64/4 float4
        ((float4*)wsh)[i] = ((const float4*)W0)[i];
    for (int i = tid; i < 4096; i += 256) {       // X tile: 128 rows * 32 float4
        int r = i >> 5, kq = i & 31;
        int gr = row0 + r;
        float4 v = make_float4(0.f, 0.f, 0.f, 0.f);
        if (gr < Nn) v = ((const float4*)X)[gr * 32 + kq];
        *(float4*)&ssh[r * 132 + kq * 4] = v;
    }
    __syncthreads();

    const int rg = tid >> 4;      // 0..15  (8 rows each)
    const int og = tid & 15;      // 0..15  (4 cols each)
    float4 acc[8];
    #pragma unroll
    for (int i = 0; i < 8; i++) acc[i] = make_float4(0.f, 0.f, 0.f, 0.f);

    #pragma unroll
    for (int k4 = 0; k4 < 32; k4++) {
        float4 wv0 = *(float4*)&wsh[(k4 * 4 + 0) * 64 + og * 4];
        float4 wv1 = *(float4*)&wsh[(k4 * 4 + 1) * 64 + og * 4];
        float4 wv2 = *(float4*)&wsh[(k4 * 4 + 2) * 64 + og * 4];
        float4 wv3 = *(float4*)&wsh[(k4 * 4 + 3) * 64 + og * 4];
        #pragma unroll
        for (int i = 0; i < 8; i++) {
            float4 sv = *(float4*)&ssh[(rg * 8 + i) * 132 + k4 * 4];
            fma4(acc[i], sv.x, wv0); fma4(acc[i], sv.y, wv1);
            fma4(acc[i], sv.z, wv2); fma4(acc[i], sv.w, wv3);
        }
    }

    float4 bv = __ldg((const float4*)&b0[og * 4]);
    #pragma unroll
    for (int i = 0; i < 8; i++) {
        int gr = row0 + rg * 8 + i;
        if (gr < Nn) {
            float4 v;
            v.x = fmaxf(acc[i].x + bv.x, 0.f);
            v.y = fmaxf(acc[i].y + bv.y, 0.f);
            v.z = fmaxf(acc[i].z + bv.z, 0.f);
            v.w = fmaxf(acc[i].w + bv.w, 0.f);
            int idx = gr * HID + og * 4;
            *(float4*)&g_x [idx] = v;
            *(float4*)&g_x0[idx] = v;
            float4 a = make_float4(C0 * v.x, C0 * v.y, C0 * v.z, C0 * v.w);
            *(float4*)&g_agg[idx] = a;
        }
    }
}

// --- mid layer: h = (1-b)*s + b*(s@Wc), s = 0.9*agg; accumulate BN sums ----
__global__ void k_gemm_bn(const float* __restrict__ Wc, float beta) {
    extern __shared__ float sm[];
    float* ssh = sm;               // 128 x 68 (padded)
    float* wsh = sm + 128 * 68;    // 64 x 64
    __shared__ float bsum[HID], bsq[HID];
    const int tid  = threadIdx.x;
    const int row0 = blockIdx.x * 128;
    if (tid < HID) { bsum[tid] = 0.f; bsq[tid] = 0.f; }

    for (int i = tid; i < 1024; i += 256)         // Wc: 64*64/4 float4
        ((float4*)wsh)[i] = ((const float4*)Wc)[i];
    for (int i = tid; i < 2048; i += 256) {       // s tile: 128 rows * 16 float4
        int r = i >> 4, kq = i & 15;
        int gr = row0 + r;
        float4 v = make_float4(0.f, 0.f, 0.f, 0.f);
        if (gr < Nn) {
            v = *(const float4*)&g_agg[gr * HID + kq * 4];
            v.x *= (1.0f - ALPHA); v.y *= (1.0f - ALPHA);
            v.z *= (1.0f - ALPHA); v.w *= (1.0f - ALPHA);
        }
        *(float4*)&ssh[r * 68 + kq * 4] = v;
    }
    __syncthreads();

    const int rg = tid >> 4;
    const int og = tid & 15;
    float4 acc[8];
    #pragma unroll
    for (int i = 0; i < 8; i++) acc[i] = make_float4(0.f, 0.f, 0.f, 0.f);

    #pragma unroll
    for (int k4 = 0; k4 < 16; k4++) {
        float4 wv0 = *(float4*)&wsh[(k4 * 4 + 0) * 64 + og * 4];
        float4 wv1 = *(float4*)&wsh[(k4 * 4 + 1) * 64 + og * 4];
        float4 wv2 = *(float4*)&wsh[(k4 * 4 + 2) * 64 + og * 4];
        float4 wv3 = *(float4*)&wsh[(k4 * 4 + 3) * 64 + og * 4];
        #pragma unroll
        for (int i = 0; i < 8; i++) {
            float4 sv = *(float4*)&ssh[(rg * 8 + i) * 68 + k4 * 4];
            fma4(acc[i], sv.x, wv0); fma4(acc[i], sv.y, wv1);
            fma4(acc[i], sv.z, wv2); fma4(acc[i], sv.w, wv3);
        }
    }

    const float ombeta = 1.0f - beta;
    float4 lsum = make_float4(0.f, 0.f, 0.f, 0.f);
    float4 lsq  = make_float4(0.f, 0.f, 0.f, 0.f);
    #pragma unroll
    for (int i = 0; i < 8; i++) {
        int r = rg * 8 + i;
        int gr = row0 + r;
        if (gr < Nn) {
            float4 sv = *(float4*)&ssh[r * 68 + og * 4];
            float4 h;
            h.x = ombeta * sv.x + beta * acc[i].x;
            h.y = ombeta * sv.y + beta * acc[i].y;
            h.z = ombeta * sv.z + beta * acc[i].z;
            h.w = ombeta * sv.w + beta * acc[i].w;
            *(float4*)&g_h[gr * HID + og * 4] = h;
            lsum.x += h.x; lsum.y += h.y; lsum.z += h.z; lsum.w += h.w;
            lsq.x += h.x * h.x; lsq.y += h.y * h.y;
            lsq.z += h.z * h.z; lsq.w += h.w * h.w;
        }
    }
    atomicAdd(&bsum[og * 4 + 0], lsum.x); atomicAdd(&bsum[og * 4 + 1], lsum.y);
    atomicAdd(&bsum[og * 4 + 2], lsum.z); atomicAdd(&bsum[og * 4 + 3], lsum.w);
    atomicAdd(&bsq [og * 4 + 0], lsq.x);  atomicAdd(&bsq [og * 4 + 1], lsq.y);
    atomicAdd(&bsq [og * 4 + 2], lsq.z);  atomicAdd(&bsq [og * 4 + 3], lsq.w);
    __syncthreads();
    if (tid < HID) {
        atomicAdd(&g_bnsum[tid], bsum[tid]);
        atomicAdd(&g_bnsq [tid], bsq [tid]);
    }
}

// --- BN apply + residual + relu; seed agg for next layer -------------------
__global__ void k_post(const float* __restrict__ gamma,
                       const float* __restrict__ bb) {
    int t = blockIdx.x * 256 + threadIdx.x;   // grid exactly Nn*16
    int n = t >> 4, q = t & 15;
    if (n >= Nn) return;
    int c = q * 4;
    int idx = n * HID + c;
    const float invN = 1.0f / (float)Nn;

    float4 h  = *(float4*)&g_h[idx];
    float4 xo = *(float4*)&g_x[idx];
    float4 v;
    {
        float m = g_bnsum[c + 0] * invN;
        float var = g_bnsq[c + 0] * invN - m * m;
        v.x = (h.x - m) * rsqrtf(var + BN_EPS) * __ldg(&gamma[c + 0]) + __ldg(&bb[c + 0]) + xo.x;
    }
    {
        float m = g_bnsum[c + 1] * invN;
        float var = g_bnsq[c + 1] * invN - m * m;
        v.y = (h.y - m) * rsqrtf(var + BN_EPS) * __ldg(&gamma[c + 1]) + __ldg(&bb[c + 1]) + xo.y;
    }
    {
        float m = g_bnsum[c + 2] * invN;
        float var = g_bnsq[c + 2] * invN - m * m;
        v.z = (h.z - m) * rsqrtf(var + BN_EPS) * __ldg(&gamma[c + 2]) + __ldg(&bb[c + 2]) + xo.z;
    }
    {
        float m = g_bnsum[c + 3] * invN;
        float var = g_bnsq[c + 3] * invN - m * m;
        v.w = (h.w - m) * rsqrtf(var + BN_EPS) * __ldg(&gamma[c + 3]) + __ldg(&bb[c + 3]) + xo.w;
    }
    v.x = fmaxf(v.x, 0.f); v.y = fmaxf(v.y, 0.f);
    v.z = fmaxf(v.z, 0.f); v.w = fmaxf(v.w, 0.f);
    *(float4*)&g_x[idx] = v;

    float4 x0v = *(float4*)&g_x0[idx];
    float4 a = make_float4(C0 * x0v.x, C0 * x0v.y, C0 * x0v.z, C0 * x0v.w);
    *(float4*)&g_agg[idx] = a;
}

// --- final: out = x @ W1 + b1  (K = 64) ------------------------------------
__global__ void k_out(const float* __restrict__ W1,
                      const float* __restrict__ b1,
                      float* __restrict__ out) {
    extern __shared__ float sm[];
    float* ssh = sm;               // 128 x 68
    float* wsh = sm + 128 * 68;    // 64 x 64
    const int tid  = threadIdx.x;
    const int row0 = blockIdx.x * 128;

    for (int i = tid; i < 1024; i += 256)
        ((float4*)wsh)[i] = ((const float4*)W1)[i];
    for (int i = tid; i < 2048; i += 256) {
        int r = i >> 4, kq = i & 15;
        int gr = row0 + r;
        float4 v = make_float4(0.f, 0.f, 0.f, 0.f);
        if (gr < Nn) v = *(const float4*)&g_x[gr * HID + kq * 4];
        *(float4*)&ssh[r * 68 + kq * 4] = v;
    }
    __syncthreads();

    const int rg = tid >> 4;
    const int og = tid & 15;
    float4 acc[8];
    #pragma unroll
    for (int i = 0; i < 8; i++) acc[i] = make_float4(0.f, 0.f, 0.f, 0.f);

    #pragma unroll
    for (int k4 = 0; k4 < 16; k4++) {
        float4 wv0 = *(float4*)&wsh[(k4 * 4 + 0) * 64 + og * 4];
        float4 wv1 = *(float4*)&wsh[(k4 * 4 + 1) * 64 + og * 4];
        float4 wv2 = *(float4*)&wsh[(k4 * 4 + 2) * 64 + og * 4];
        float4 wv3 = *(float4*)&wsh[(k4 * 4 + 3) * 64 + og * 4];
        #pragma unroll
        for (int i = 0; i < 8; i++) {
            float4 sv = *(float4*)&ssh[(rg * 8 + i) * 68 + k4 * 4];
            fma4(acc[i], sv.x, wv0); fma4(acc[i], sv.y, wv1);
            fma4(acc[i], sv.z, wv2); fma4(acc[i], sv.w, wv3);
        }
    }

    float4 bv = __ldg((const float4*)&b1[og * 4]);
    #pragma unroll
    for (int i = 0; i < 8; i++) {
        int gr = row0 + rg * 8 + i;
        if (gr < Nn) {
            float4 v;
            v.x = acc[i].x + bv.x; v.y = acc[i].y + bv.y;
            v.z = acc[i].z + bv.z; v.w = acc[i].w + bv.w;
            *(float4*)&out[gr * HID + og * 4] = v;
        }
    }
}

// ---------------------------------------------------------------------------
extern "C" void kernel_launch(void* const* d_in, const int* in_sizes, int n_in,
                              void* d_out, int out_size) {
    const float* x     = (const float*)d_in[0];
    const int*   ei    = (const int*)  d_in[1];
    const float* W0    = (const float*)d_in[2];
    const float* b0    = (const float*)d_in[3];
    const float* convw = (const float*)d_in[4];
    const float* gamma = (const float*)d_in[5];
    const float* betab = (const float*)d_in[6];
    const float* W1    = (const float*)d_in[7];
    const float* b1    = (const float*)d_in[8];
    float* out = (float*)d_out;

    const int SMEM_MLP0 = (128 * 132 + 128 * 64) * 4;   // 100352 B
    const int SMEM_G64  = (128 * 68  + 64  * 64) * 4;   // 51200 B
    cudaFuncSetAttribute(k_mlp0,    cudaFuncAttributeMaxDynamicSharedMemorySize, SMEM_MLP0);
    cudaFuncSetAttribute(k_gemm_bn, cudaFuncAttributeMaxDynamicSharedMemorySize, SMEM_G64);
    cudaFuncSetAttribute(k_out,     cudaFuncAttributeMaxDynamicSharedMemorySize, SMEM_G64);

    const int GB = (Nn + 127) / 128;          // 782 gemm blocks

    k_zero_deg<<<(Nn + 255) / 256, 256>>>();
    k_deg<<<(Ee + 255) / 256, 256>>>(ei);
    k_ew <<<(Ee + 255) / 256, 256>>>(ei);
    k_mlp0<<<GB, 256, SMEM_MLP0>>>(x, W0, b0);

    for (int i = 0; i < 4; i++) {
        k_spmm<<<(Ee * 16) / 256, 256>>>(ei);
        float beta = (float)log(0.5 / (double)(i + 1) + 1.0);
        k_gemm_bn<<<GB, 256, SMEM_G64>>>(convw + i * HID * HID, beta);
        k_post<<<(Nn * 16 + 255) / 256, 256>>>(gamma + i * HID, betab + i * HID);
    }

    k_out<<<GB, 256, SMEM_G64>>>(W1, b1, out);
}

// round 7
// speedup vs baseline: 1.1992x; 1.1992x over previous
#include <cuda_runtime.h>
#include <cuda_bf16.h>
#include <math.h>

// ---------------------------------------------------------------------------
// GCN2 (GCNII) forward:  N=100000, E=1e6, IN=128, HID=64, OUT=64, L=4
//
// R6 structure:
//   prep:  cnt[row]  (int histogram)  ->  2-level scan -> rowstart
//          scatter edges into CSR:  g_edge[pos] = (col, w)  w = dinv_r*dinv_c
//   x = relu(X@W0+b0); x0 = x
//   per layer:
//     s[row] = 0.9 * sum_csr(w * x[col]) + 0.1 * x0[row]      (gather SPMM)
//     h = (1-b)*s + b*(s@Wc)  + BN partial sums (atomics)
//     x = relu(BN(h)*gamma + beta + x)
//   out = x @ W1 + b1
// ---------------------------------------------------------------------------

#define Nn   100000
#define Ee   1000000
#define HID  64
#define BN_EPS 1e-5f

#define RPB   512                      // rows per scan block
#define NBLK  ((Nn + RPB - 1) / RPB)   // 196

// ---- scratch (device globals; allocation-free) ----
__device__ float g_x  [Nn * HID];
__device__ float g_x0 [Nn * HID];
__device__ float g_s  [Nn * HID];
__device__ float g_h  [Nn * HID];
__device__ int2  g_edge[Ee];           // (col, w bits) CSR-sorted by row
__device__ int   g_cnt[Nn];
__device__ int   g_cur[Nn];
__device__ int   g_rowstart[Nn];
__device__ int   g_blocksum[NBLK];
__device__ int   g_blockoff[NBLK];
__device__ float g_bnsum[HID];
__device__ float g_bnsq [HID];

// ---------------------------------------------------------------------------
// CSR construction
// ---------------------------------------------------------------------------
__global__ void k_zero() {
    int i = blockIdx.x * blockDim.x + threadIdx.x;
    if (i < Nn) { g_cnt[i] = 0; g_cur[i] = 0; }
}

__global__ void k_count(const int* __restrict__ ei) {
    int e = blockIdx.x * blockDim.x + threadIdx.x;
    if (e < Ee) atomicAdd(&g_cnt[ei[e]], 1);
}

__global__ void k_scanA() {            // NBLK blocks x RPB threads: block sums
    __shared__ int sh[RPB];
    int r = blockIdx.x * RPB + threadIdx.x;
    sh[threadIdx.x] = (r < Nn) ? g_cnt[r] : 0;
    __syncthreads();
    for (int off = RPB / 2; off > 0; off >>= 1) {
        if (threadIdx.x < off) sh[threadIdx.x] += sh[threadIdx.x + off];
        __syncthreads();
    }
    if (threadIdx.x == 0) g_blocksum[blockIdx.x] = sh[0];
}

__global__ void k_scanB() {            // 1 block x 256: exclusive scan of block sums
    __shared__ int sh[256];
    int tid = threadIdx.x;
    int v = (tid < NBLK) ? g_blocksum[tid] : 0;
    sh[tid] = v;
    __syncthreads();
    for (int off = 1; off < 256; off <<= 1) {
        int t = (tid >= off) ? sh[tid - off] : 0;
        __syncthreads();
        sh[tid] += t;
        __syncthreads();
    }
    if (tid < NBLK) g_blockoff[tid] = sh[tid] - v;
}

__global__ void k_scanC() {            // NBLK blocks x RPB: exclusive rowstart
    __shared__ int sh[RPB];
    int tid = threadIdx.x;
    int r = blockIdx.x * RPB + tid;
    int v = (r < Nn) ? g_cnt[r] : 0;
    sh[tid] = v;
    __syncthreads();
    for (int off = 1; off < RPB; off <<= 1) {
        int t = (tid >= off) ? sh[tid - off] : 0;
        __syncthreads();
        sh[tid] += t;
        __syncthreads();
    }
    if (r < Nn) g_rowstart[r] = sh[tid] - v + g_blockoff[blockIdx.x];
}

__device__ __forceinline__ float dinv_of(int d) {
    return d > 0 ? rsqrtf((float)d) : 0.0f;
}

__global__ void k_scatter(const int* __restrict__ ei) {
    int e = blockIdx.x * blockDim.x + threadIdx.x;
    if (e >= Ee) return;
    int row = ei[e];
    int col = ei[Ee + e];
    int pos = g_rowstart[row] + atomicAdd(&g_cur[row], 1);
    float w = dinv_of(g_cnt[row]) * dinv_of(g_cnt[col]);
    g_edge[pos] = make_int2(col, __float_as_int(w));
}

// ---------------------------------------------------------------------------
// SPMM (gather, CSR): one warp per row, each lane owns 2 of 64 channels.
//   s[row] = 0.9 * sum(w * x[col]) + 0.1 * x0[row]
// Also zeroes BN accumulators for the following GEMM+BN kernel.
// ---------------------------------------------------------------------------
__global__ void k_spmm_csr() {
    if (blockIdx.x == 0 && threadIdx.x < HID) {
        g_bnsum[threadIdx.x] = 0.0f;
        g_bnsq [threadIdx.x] = 0.0f;
    }
    int warp = (blockIdx.x * 256 + threadIdx.x) >> 5;
    int lane = threadIdx.x & 31;
    if (warp >= Nn) return;

    int start = g_rowstart[warp];
    int deg   = g_cnt[warp];
    const float2* xp = (const float2*)g_x;

    float2 acc = make_float2(0.f, 0.f);
    #pragma unroll 4
    for (int j = 0; j < deg; j++) {
        int2 em = __ldg(&g_edge[start + j]);
        float w = __int_as_float(em.y);
        float2 v = __ldg(&xp[em.x * 32 + lane]);
        acc.x = fmaf(w, v.x, acc.x);
        acc.y = fmaf(w, v.y, acc.y);
    }
    float2 x0v = __ldg(&((const float2*)g_x0)[warp * 32 + lane]);
    float2 s;
    s.x = 0.9f * acc.x + 0.1f * x0v.x;
    s.y = 0.9f * acc.y + 0.1f * x0v.y;
    ((float2*)g_s)[warp * 32 + lane] = s;
}

// ---------------------------------------------------------------------------
// Tiled fp32 GEMM machinery: block = 256 threads, 128 rows/block,
// thread tile = 8 rows x 4 cols, all LDS.128.
// ---------------------------------------------------------------------------
__device__ __forceinline__ void fma4(float4& a, float s, const float4& b) {
    a.x = fmaf(s, b.x, a.x);
    a.y = fmaf(s, b.y, a.y);
    a.z = fmaf(s, b.z, a.z);
    a.w = fmaf(s, b.w, a.w);
}

// --- layer 0: x = relu(X@W0 + b0); x0 = x  (K = 128, chunked 2x64) ---------
__global__ void k_mlp0(const float* __restrict__ X,
                       const float* __restrict__ W0,
                       const float* __restrict__ b0) {
    extern __shared__ float sm[];
    float* ssh = sm;               // 128 rows x 68 (padded), one 64-K chunk
    float* wsh = sm + 128 * 68;    // 64 x 64 chunk of W0
    const int tid  = threadIdx.x;
    const int row0 = blockIdx.x * 128;
    const int rg = tid >> 4;       // 0..15  (8 rows each)
    const int og = tid & 15;       // 0..15  (4 cols each)

    float4 acc[8];
    #pragma unroll
    for (int i = 0; i < 8; i++) acc[i] = make_float4(0.f, 0.f, 0.f, 0.f);

    for (int ko = 0; ko < 2; ko++) {
        if (ko) __syncthreads();
        for (int i = tid; i < 1024; i += 256)   // W0[ko*64 + r][:] 64 rows
            ((float4*)wsh)[i] = ((const float4*)W0)[ko * 1024 + i];
        for (int i = tid; i < 2048; i += 256) { // X tile: 128 rows x 16 float4
            int r = i >> 4, kq = i & 15;
            int gr = row0 + r;
            float4 v = make_float4(0.f, 0.f, 0.f, 0.f);
            if (gr < Nn) v = ((const float4*)X)[gr * 32 + ko * 16 + kq];
            *(float4*)&ssh[r * 68 + kq * 4] = v;
        }
        __syncthreads();

        #pragma unroll
        for (int k4 = 0; k4 < 16; k4++) {
            float4 wv0 = *(float4*)&wsh[(k4 * 4 + 0) * 64 + og * 4];
            float4 wv1 = *(float4*)&wsh[(k4 * 4 + 1) * 64 + og * 4];
            float4 wv2 = *(float4*)&wsh[(k4 * 4 + 2) * 64 + og * 4];
            float4 wv3 = *(float4*)&wsh[(k4 * 4 + 3) * 64 + og * 4];
            #pragma unroll
            for (int i = 0; i < 8; i++) {
                float4 sv = *(float4*)&ssh[(rg * 8 + i) * 68 + k4 * 4];
                fma4(acc[i], sv.x, wv0); fma4(acc[i], sv.y, wv1);
                fma4(acc[i], sv.z, wv2); fma4(acc[i], sv.w, wv3);
            }
        }
    }

    float4 bv = __ldg((const float4*)&b0[og * 4]);
    #pragma unroll
    for (int i = 0; i < 8; i++) {
        int gr = row0 + rg * 8 + i;
        if (gr < Nn) {
            float4 v;
            v.x = fmaxf(acc[i].x + bv.x, 0.f);
            v.y = fmaxf(acc[i].y + bv.y, 0.f);
            v.z = fmaxf(acc[i].z + bv.z, 0.f);
            v.w = fmaxf(acc[i].w + bv.w, 0.f);
            int idx = gr * HID + og * 4;
            *(float4*)&g_x [idx] = v;
            *(float4*)&g_x0[idx] = v;
        }
    }
}

// --- mid layer: h = (1-b)*s + b*(s@Wc); accumulate BN sums -----------------
__global__ void k_gemm_bn(const float* __restrict__ Wc, float beta) {
    extern __shared__ float sm[];
    float* ssh = sm;               // 128 x 68 (padded)
    float* wsh = sm + 128 * 68;    // 64 x 64
    __shared__ float bsum[HID], bsq[HID];
    const int tid  = threadIdx.x;
    const int row0 = blockIdx.x * 128;
    if (tid < HID) { bsum[tid] = 0.f; bsq[tid] = 0.f; }

    for (int i = tid; i < 1024; i += 256)
        ((float4*)wsh)[i] = ((const float4*)Wc)[i];
    for (int i = tid; i < 2048; i += 256) {
        int r = i >> 4, kq = i & 15;
        int gr = row0 + r;
        float4 v = make_float4(0.f, 0.f, 0.f, 0.f);
        if (gr < Nn) v = *(const float4*)&g_s[gr * HID + kq * 4];
        *(float4*)&ssh[r * 68 + kq * 4] = v;
    }
    __syncthreads();

    const int rg = tid >> 4;
    const int og = tid & 15;
    float4 acc[8];
    #pragma unroll
    for (int i = 0; i < 8; i++) acc[i] = make_float4(0.f, 0.f, 0.f, 0.f);

    #pragma unroll
    for (int k4 = 0; k4 < 16; k4++) {
        float4 wv0 = *(float4*)&wsh[(k4 * 4 + 0) * 64 + og * 4];
        float4 wv1 = *(float4*)&wsh[(k4 * 4 + 1) * 64 + og * 4];
        float4 wv2 = *(float4*)&wsh[(k4 * 4 + 2) * 64 + og * 4];
        float4 wv3 = *(float4*)&wsh[(k4 * 4 + 3) * 64 + og * 4];
        #pragma unroll
        for (int i = 0; i < 8; i++) {
            float4 sv = *(float4*)&ssh[(rg * 8 + i) * 68 + k4 * 4];
            fma4(acc[i], sv.x, wv0); fma4(acc[i], sv.y, wv1);
            fma4(acc[i], sv.z, wv2); fma4(acc[i], sv.w, wv3);
        }
    }

    const float ombeta = 1.0f - beta;
    float4 lsum = make_float4(0.f, 0.f, 0.f, 0.f);
    float4 lsq  = make_float4(0.f, 0.f, 0.f, 0.f);
    #pragma unroll
    for (int i = 0; i < 8; i++) {
        int r = rg * 8 + i;
        int gr = row0 + r;
        if (gr < Nn) {
            float4 sv = *(float4*)&ssh[r * 68 + og * 4];
            float4 h;
            h.x = ombeta * sv.x + beta * acc[i].x;
            h.y = ombeta * sv.y + beta * acc[i].y;
            h.z = ombeta * sv.z + beta * acc[i].z;
            h.w = ombeta * sv.w + beta * acc[i].w;
            *(float4*)&g_h[gr * HID + og * 4] = h;
            lsum.x += h.x; lsum.y += h.y; lsum.z += h.z; lsum.w += h.w;
            lsq.x += h.x * h.x; lsq.y += h.y * h.y;
            lsq.z += h.z * h.z; lsq.w += h.w * h.w;
        }
    }
    atomicAdd(&bsum[og * 4 + 0], lsum.x); atomicAdd(&bsum[og * 4 + 1], lsum.y);
    atomicAdd(&bsum[og * 4 + 2], lsum.z); atomicAdd(&bsum[og * 4 + 3], lsum.w);
    atomicAdd(&bsq [og * 4 + 0], lsq.x);  atomicAdd(&bsq [og * 4 + 1], lsq.y);
    atomicAdd(&bsq [og * 4 + 2], lsq.z);  atomicAdd(&bsq [og * 4 + 3], lsq.w);
    __syncthreads();
    if (tid < HID) {
        atomicAdd(&g_bnsum[tid], bsum[tid]);
        atomicAdd(&g_bnsq [tid], bsq [tid]);
    }
}

// --- BN apply + residual + relu -> g_x -------------------------------------
__global__ void k_post(const float* __restrict__ gamma,
                       const float* __restrict__ bb) {
    int t = blockIdx.x * 256 + threadIdx.x;   // grid covers Nn*16
    int n = t >> 4, q = t & 15;
    if (n >= Nn) return;
    int c = q * 4;
    int idx = n * HID + c;
    const float invN = 1.0f / (float)Nn;

    float4 h  = *(float4*)&g_h[idx];
    float4 xo = *(float4*)&g_x[idx];
    float4 v;
    {
        float m = g_bnsum[c + 0] * invN;
        float var = g_bnsq[c + 0] * invN - m * m;
        v.x = (h.x - m) * rsqrtf(var + BN_EPS) * __ldg(&gamma[c + 0]) + __ldg(&bb[c + 0]) + xo.x;
    }
    {
        float m = g_bnsum[c + 1] * invN;
        float var = g_bnsq[c + 1] * invN - m * m;
        v.y = (h.y - m) * rsqrtf(var + BN_EPS) * __ldg(&gamma[c + 1]) + __ldg(&bb[c + 1]) + xo.y;
    }
    {
        float m = g_bnsum[c + 2] * invN;
        float var = g_bnsq[c + 2] * invN - m * m;
        v.z = (h.z - m) * rsqrtf(var + BN_EPS) * __ldg(&gamma[c + 2]) + __ldg(&bb[c + 2]) + xo.z;
    }
    {
        float m = g_bnsum[c + 3] * invN;
        float var = g_bnsq[c + 3] * invN - m * m;
        v.w = (h.w - m) * rsqrtf(var + BN_EPS) * __ldg(&gamma[c + 3]) + __ldg(&bb[c + 3]) + xo.w;
    }
    v.x = fmaxf(v.x, 0.f); v.y = fmaxf(v.y, 0.f);
    v.z = fmaxf(v.z, 0.f); v.w = fmaxf(v.w, 0.f);
    *(float4*)&g_x[idx] = v;
}

// --- final: out = x @ W1 + b1  (K = 64) ------------------------------------
__global__ void k_out(const float* __restrict__ W1,
                      const float* __restrict__ b1,
                      float* __restrict__ out) {
    extern __shared__ float sm[];
    float* ssh = sm;               // 128 x 68
    float* wsh = sm + 128 * 68;    // 64 x 64
    const int tid  = threadIdx.x;
    const int row0 = blockIdx.x * 128;

    for (int i = tid; i < 1024; i += 256)
        ((float4*)wsh)[i] = ((const float4*)W1)[i];
    for (int i = tid; i < 2048; i += 256) {
        int r = i >> 4, kq = i & 15;
        int gr = row0 + r;
        float4 v = make_float4(0.f, 0.f, 0.f, 0.f);
        if (gr < Nn) v = *(const float4*)&g_x[gr * HID + kq * 4];
        *(float4*)&ssh[r * 68 + kq * 4] = v;
    }
    __syncthreads();

    const int rg = tid >> 4;
    const int og = tid & 15;
    float4 acc[8];
    #pragma unroll
    for (int i = 0; i < 8; i++) acc[i] = make_float4(0.f, 0.f, 0.f, 0.f);

    #pragma unroll
    for (int k4 = 0; k4 < 16; k4++) {
        float4 wv0 = *(float4*)&wsh[(k4 * 4 + 0) * 64 + og * 4];
        float4 wv1 = *(float4*)&wsh[(k4 * 4 + 1) * 64 + og * 4];
        float4 wv2 = *(float4*)&wsh[(k4 * 4 + 2) * 64 + og * 4];
        float4 wv3 = *(float4*)&wsh[(k4 * 4 + 3) * 64 + og * 4];
        #pragma unroll
        for (int i = 0; i < 8; i++) {
            float4 sv = *(float4*)&ssh[(rg * 8 + i) * 68 + k4 * 4];
            fma4(acc[i], sv.x, wv0); fma4(acc[i], sv.y, wv1);
            fma4(acc[i], sv.z, wv2); fma4(acc[i], sv.w, wv3);
        }
    }

    float4 bv = __ldg((const float4*)&b1[og * 4]);
    #pragma unroll
    for (int i = 0; i < 8; i++) {
        int gr = row0 + rg * 8 + i;
        if (gr < Nn) {
            float4 v;
            v.x = acc[i].x + bv.x; v.y = acc[i].y + bv.y;
            v.z = acc[i].z + bv.z; v.w = acc[i].w + bv.w;
            *(float4*)&out[gr * HID + og * 4] = v;
        }
    }
}

// ---------------------------------------------------------------------------
extern "C" void kernel_launch(void* const* d_in, const int* in_sizes, int n_in,
                              void* d_out, int out_size) {
    const float* x     = (const float*)d_in[0];
    const int*   ei    = (const int*)  d_in[1];
    const float* W0    = (const float*)d_in[2];
    const float* b0    = (const float*)d_in[3];
    const float* convw = (const float*)d_in[4];
    const float* gamma = (const float*)d_in[5];
    const float* betab = (const float*)d_in[6];
    const float* W1    = (const float*)d_in[7];
    const float* b1    = (const float*)d_in[8];
    float* out = (float*)d_out;

    const int SMEM_G64 = (128 * 68 + 64 * 64) * 4;   // 51200 B
    cudaFuncSetAttribute(k_mlp0,    cudaFuncAttributeMaxDynamicSharedMemorySize, SMEM_G64);
    cudaFuncSetAttribute(k_gemm_bn, cudaFuncAttributeMaxDynamicSharedMemorySize, SMEM_G64);
    cudaFuncSetAttribute(k_out,     cudaFuncAttributeMaxDynamicSharedMemorySize, SMEM_G64);

    const int GB = (Nn + 127) / 128;          // 782 gemm blocks
    const int EB = (Ee + 255) / 256;          // edge blocks

    // CSR build (overlappable with k_mlp0 in principle; stream-ordered here)
    k_zero   <<<(Nn + 255) / 256, 256>>>();
    k_count  <<<EB, 256>>>(ei);
    k_scanA  <<<NBLK, RPB>>>();
    k_scanB  <<<1, 256>>>();
    k_scanC  <<<NBLK, RPB>>>();
    k_scatter<<<EB, 256>>>(ei);

    k_mlp0<<<GB, 256, SMEM_G64>>>(x, W0, b0);

    const int SPB = (Nn * 32 + 255) / 256;    // 8 warps (rows) per block
    for (int i = 0; i < 4; i++) {
        k_spmm_csr<<<SPB, 256>>>();
        float beta = (float)log(0.5 / (double)(i + 1) + 1.0);
        k_gemm_bn<<<GB, 256, SMEM_G64>>>(convw + i * HID * HID, beta);
        k_post<<<(Nn * 16 + 255) / 256, 256>>>(gamma + i * HID, betab + i * HID);
    }

    k_out<<<GB, 256, SMEM_G64>>>(W1, b1, out);
}

// round 8
// speedup vs baseline: 1.2337x; 1.0287x over previous
#include <cuda_runtime.h>
#include <cuda_bf16.h>
#include <cuda_fp16.h>
#include <math.h>

// ---------------------------------------------------------------------------
// GCN2 (GCNII) forward:  N=100000, E=1e6, IN=128, HID=64, OUT=64, L=4
//
// R8 structure:
//   stream fork:  [s2] CSR build (count -> scans -> scatter(col,w))
//                 [s1] x = relu(X@W0+b0); x0 = x; xh = fp16(x)
//   join, then per layer on s1:
//     s[row] = 0.9 * sum_csr(w * fp16(x)[col]) + 0.1 * x0[row]   (gather SPMM)
//     h = (1-b)*s + b*(s@Wc)  + BN partial sums (atomics)
//     x = relu(BN(h)*gamma + beta + x);  xh = fp16(x)
//   out = x @ W1 + b1            (all dense math fp32)
// ---------------------------------------------------------------------------

#define Nn   100000
#define Ee   1000000
#define HID  64
#define BN_EPS 1e-5f

#define RPB   512                      // rows per scan block
#define NBLK  ((Nn + RPB - 1) / RPB)   // 196

// ---- scratch (device globals; allocation-free) ----
__device__ float   g_x  [Nn * HID];
__device__ float   g_x0 [Nn * HID];
__device__ float   g_s  [Nn * HID];
__device__ float   g_h  [Nn * HID];
__device__ __half2 g_xh [Nn * 32];     // fp16 shadow of g_x (gather operand)
__device__ int2    g_edge[Ee];         // (col, w bits) CSR-sorted by row
__device__ int     g_cnt[Nn];
__device__ int     g_cur[Nn];
__device__ int     g_rowstart[Nn];
__device__ int     g_blocksum[NBLK];
__device__ int     g_blockoff[NBLK];
__device__ float   g_bnsum[HID];
__device__ float   g_bnsq [HID];

// ---------------------------------------------------------------------------
// CSR construction
// ---------------------------------------------------------------------------
__global__ void k_zero() {
    int i = blockIdx.x * blockDim.x + threadIdx.x;
    if (i < Nn) { g_cnt[i] = 0; g_cur[i] = 0; }
}

__global__ void k_count(const int* __restrict__ ei) {
    int e = blockIdx.x * blockDim.x + threadIdx.x;
    if (e < Ee) atomicAdd(&g_cnt[ei[e]], 1);
}

__global__ void k_scanA() {            // NBLK blocks x RPB threads: block sums
    __shared__ int sh[RPB];
    int r = blockIdx.x * RPB + threadIdx.x;
    sh[threadIdx.x] = (r < Nn) ? g_cnt[r] : 0;
    __syncthreads();
    for (int off = RPB / 2; off > 0; off >>= 1) {
        if (threadIdx.x < off) sh[threadIdx.x] += sh[threadIdx.x + off];
        __syncthreads();
    }
    if (threadIdx.x == 0) g_blocksum[blockIdx.x] = sh[0];
}

__global__ void k_scanB() {            // 1 block x 256: exclusive scan of block sums
    __shared__ int sh[256];
    int tid = threadIdx.x;
    int v = (tid < NBLK) ? g_blocksum[tid] : 0;
    sh[tid] = v;
    __syncthreads();
    for (int off = 1; off < 256; off <<= 1) {
        int t = (tid >= off) ? sh[tid - off] : 0;
        __syncthreads();
        sh[tid] += t;
        __syncthreads();
    }
    if (tid < NBLK) g_blockoff[tid] = sh[tid] - v;
}

__global__ void k_scanC() {            // NBLK blocks x RPB: exclusive rowstart
    __shared__ int sh[RPB];
    int tid = threadIdx.x;
    int r = blockIdx.x * RPB + tid;
    int v = (r < Nn) ? g_cnt[r] : 0;
    sh[tid] = v;
    __syncthreads();
    for (int off = 1; off < RPB; off <<= 1) {
        int t = (tid >= off) ? sh[tid - off] : 0;
        __syncthreads();
        sh[tid] += t;
        __syncthreads();
    }
    if (r < Nn) g_rowstart[r] = sh[tid] - v + g_blockoff[blockIdx.x];
}

__device__ __forceinline__ float dinv_of(int d) {
    return d > 0 ? rsqrtf((float)d) : 0.0f;
}

__global__ void k_scatter(const int* __restrict__ ei) {
    int e = blockIdx.x * blockDim.x + threadIdx.x;
    if (e >= Ee) return;
    int row = ei[e];
    int col = ei[Ee + e];
    int pos = g_rowstart[row] + atomicAdd(&g_cur[row], 1);
    float w = dinv_of(g_cnt[row]) * dinv_of(g_cnt[col]);
    g_edge[pos] = make_int2(col, __float_as_int(w));
}

// ---------------------------------------------------------------------------
// SPMM (gather, CSR): one warp per row, each lane owns 2 of 64 channels.
// Gather operand is the fp16 shadow (halves L2 traffic); accumulate fp32.
//   s[row] = 0.9 * sum(w * xh[col]) + 0.1 * x0[row]
// Also zeroes BN accumulators for the following GEMM+BN kernel.
// ---------------------------------------------------------------------------
__global__ void k_spmm_csr() {
    if (blockIdx.x == 0 && threadIdx.x < HID) {
        g_bnsum[threadIdx.x] = 0.0f;
        g_bnsq [threadIdx.x] = 0.0f;
    }
    int warp = (blockIdx.x * 256 + threadIdx.x) >> 5;
    int lane = threadIdx.x & 31;
    if (warp >= Nn) return;

    int start = g_rowstart[warp];
    int deg   = g_cnt[warp];

    float2 acc = make_float2(0.f, 0.f);
    #pragma unroll 4
    for (int j = 0; j < deg; j++) {
        int2 em = __ldg(&g_edge[start + j]);
        float w = __int_as_float(em.y);
        float2 v = __half22float2(__ldg(&g_xh[em.x * 32 + lane]));
        acc.x = fmaf(w, v.x, acc.x);
        acc.y = fmaf(w, v.y, acc.y);
    }
    float2 x0v = __ldg(&((const float2*)g_x0)[warp * 32 + lane]);
    float2 s;
    s.x = 0.9f * acc.x + 0.1f * x0v.x;
    s.y = 0.9f * acc.y + 0.1f * x0v.y;
    ((float2*)g_s)[warp * 32 + lane] = s;
}

// ---------------------------------------------------------------------------
// Tiled fp32 GEMM machinery: block = 256 threads, 128 rows/block,
// thread tile = 8 rows x 4 cols, all LDS.128.
// ---------------------------------------------------------------------------
__device__ __forceinline__ void fma4(float4& a, float s, const float4& b) {
    a.x = fmaf(s, b.x, a.x);
    a.y = fmaf(s, b.y, a.y);
    a.z = fmaf(s, b.z, a.z);
    a.w = fmaf(s, b.w, a.w);
}

__device__ __forceinline__ void store_xh(int gr, int og, const float4& v) {
    __half2 h0 = __floats2half2_rn(v.x, v.y);
    __half2 h1 = __floats2half2_rn(v.z, v.w);
    uint2 p = make_uint2(*(unsigned*)&h0, *(unsigned*)&h1);
    *(uint2*)&g_xh[gr * 32 + og * 2] = p;
}

// --- layer 0: x = relu(X@W0 + b0); x0 = x; xh = fp16(x)  (K=128, 2x64) -----
__global__ void k_mlp0(const float* __restrict__ X,
                       const float* __restrict__ W0,
                       const float* __restrict__ b0) {
    extern __shared__ float sm[];
    float* ssh = sm;               // 128 rows x 68 (padded), one 64-K chunk
    float* wsh = sm + 128 * 68;    // 64 x 64 chunk of W0
    const int tid  = threadIdx.x;
    const int row0 = blockIdx.x * 128;
    const int rg = tid >> 4;       // 0..15  (8 rows each)
    const int og = tid & 15;       // 0..15  (4 cols each)

    float4 acc[8];
    #pragma unroll
    for (int i = 0; i < 8; i++) acc[i] = make_float4(0.f, 0.f, 0.f, 0.f);

    for (int ko = 0; ko < 2; ko++) {
        if (ko) __syncthreads();
        for (int i = tid; i < 1024; i += 256)
            ((float4*)wsh)[i] = ((const float4*)W0)[ko * 1024 + i];
        for (int i = tid; i < 2048; i += 256) {
            int r = i >> 4, kq = i & 15;
            int gr = row0 + r;
            float4 v = make_float4(0.f, 0.f, 0.f, 0.f);
            if (gr < Nn) v = ((const float4*)X)[gr * 32 + ko * 16 + kq];
            *(float4*)&ssh[r * 68 + kq * 4] = v;
        }
        __syncthreads();

        #pragma unroll
        for (int k4 = 0; k4 < 16; k4++) {
            float4 wv0 = *(float4*)&wsh[(k4 * 4 + 0) * 64 + og * 4];
            float4 wv1 = *(float4*)&wsh[(k4 * 4 + 1) * 64 + og * 4];
            float4 wv2 = *(float4*)&wsh[(k4 * 4 + 2) * 64 + og * 4];
            float4 wv3 = *(float4*)&wsh[(k4 * 4 + 3) * 64 + og * 4];
            #pragma unroll
            for (int i = 0; i < 8; i++) {
                float4 sv = *(float4*)&ssh[(rg * 8 + i) * 68 + k4 * 4];
                fma4(acc[i], sv.x, wv0); fma4(acc[i], sv.y, wv1);
                fma4(acc[i], sv.z, wv2); fma4(acc[i], sv.w, wv3);
            }
        }
    }

    float4 bv = __ldg((const float4*)&b0[og * 4]);
    #pragma unroll
    for (int i = 0; i < 8; i++) {
        int gr = row0 + rg * 8 + i;
        if (gr < Nn) {
            float4 v;
            v.x = fmaxf(acc[i].x + bv.x, 0.f);
            v.y = fmaxf(acc[i].y + bv.y, 0.f);
            v.z = fmaxf(acc[i].z + bv.z, 0.f);
            v.w = fmaxf(acc[i].w + bv.w, 0.f);
            int idx = gr * HID + og * 4;
            *(float4*)&g_x [idx] = v;
            *(float4*)&g_x0[idx] = v;
            store_xh(gr, og, v);
        }
    }
}

// --- mid layer: h = (1-b)*s + b*(s@Wc); accumulate BN sums -----------------
__global__ void k_gemm_bn(const float* __restrict__ Wc, float beta) {
    extern __shared__ float sm[];
    float* ssh = sm;               // 128 x 68 (padded)
    float* wsh = sm + 128 * 68;    // 64 x 64
    __shared__ float bsum[HID], bsq[HID];
    const int tid  = threadIdx.x;
    const int row0 = blockIdx.x * 128;
    if (tid < HID) { bsum[tid] = 0.f; bsq[tid] = 0.f; }

    for (int i = tid; i < 1024; i += 256)
        ((float4*)wsh)[i] = ((const float4*)Wc)[i];
    for (int i = tid; i < 2048; i += 256) {
        int r = i >> 4, kq = i & 15;
        int gr = row0 + r;
        float4 v = make_float4(0.f, 0.f, 0.f, 0.f);
        if (gr < Nn) v = *(const float4*)&g_s[gr * HID + kq * 4];
        *(float4*)&ssh[r * 68 + kq * 4] = v;
    }
    __syncthreads();

    const int rg = tid >> 4;
    const int og = tid & 15;
    float4 acc[8];
    #pragma unroll
    for (int i = 0; i < 8; i++) acc[i] = make_float4(0.f, 0.f, 0.f, 0.f);

    #pragma unroll
    for (int k4 = 0; k4 < 16; k4++) {
        float4 wv0 = *(float4*)&wsh[(k4 * 4 + 0) * 64 + og * 4];
        float4 wv1 = *(float4*)&wsh[(k4 * 4 + 1) * 64 + og * 4];
        float4 wv2 = *(float4*)&wsh[(k4 * 4 + 2) * 64 + og * 4];
        float4 wv3 = *(float4*)&wsh[(k4 * 4 + 3) * 64 + og * 4];
        #pragma unroll
        for (int i = 0; i < 8; i++) {
            float4 sv = *(float4*)&ssh[(rg * 8 + i) * 68 + k4 * 4];
            fma4(acc[i], sv.x, wv0); fma4(acc[i], sv.y, wv1);
            fma4(acc[i], sv.z, wv2); fma4(acc[i], sv.w, wv3);
        }
    }

    const float ombeta = 1.0f - beta;
    float4 lsum = make_float4(0.f, 0.f, 0.f, 0.f);
    float4 lsq  = make_float4(0.f, 0.f, 0.f, 0.f);
    #pragma unroll
    for (int i = 0; i < 8; i++) {
        int r = rg * 8 + i;
        int gr = row0 + r;
        if (gr < Nn) {
            float4 sv = *(float4*)&ssh[r * 68 + og * 4];
            float4 h;
            h.x = ombeta * sv.x + beta * acc[i].x;
            h.y = ombeta * sv.y + beta * acc[i].y;
            h.z = ombeta * sv.z + beta * acc[i].z;
            h.w = ombeta * sv.w + beta * acc[i].w;
            *(float4*)&g_h[gr * HID + og * 4] = h;
            lsum.x += h.x; lsum.y += h.y; lsum.z += h.z; lsum.w += h.w;
            lsq.x += h.x * h.x; lsq.y += h.y * h.y;
            lsq.z += h.z * h.z; lsq.w += h.w * h.w;
        }
    }
    atomicAdd(&bsum[og * 4 + 0], lsum.x); atomicAdd(&bsum[og * 4 + 1], lsum.y);
    atomicAdd(&bsum[og * 4 + 2], lsum.z); atomicAdd(&bsum[og * 4 + 3], lsum.w);
    atomicAdd(&bsq [og * 4 + 0], lsq.x);  atomicAdd(&bsq [og * 4 + 1], lsq.y);
    atomicAdd(&bsq [og * 4 + 2], lsq.z);  atomicAdd(&bsq [og * 4 + 3], lsq.w);
    __syncthreads();
    if (tid < HID) {
        atomicAdd(&g_bnsum[tid], bsum[tid]);
        atomicAdd(&g_bnsq [tid], bsq [tid]);
    }
}

// --- BN apply + residual + relu -> g_x, g_xh -------------------------------
__global__ void k_post(const float* __restrict__ gamma,
                       const float* __restrict__ bb) {
    int t = blockIdx.x * 256 + threadIdx.x;   // grid covers Nn*16
    int n = t >> 4, q = t & 15;
    if (n >= Nn) return;
    int c = q * 4;
    int idx = n * HID + c;
    const float invN = 1.0f / (float)Nn;

    float4 h  = *(float4*)&g_h[idx];
    float4 xo = *(float4*)&g_x[idx];
    float4 v;
    {
        float m = g_bnsum[c + 0] * invN;
        float var = g_bnsq[c + 0] * invN - m * m;
        v.x = (h.x - m) * rsqrtf(var + BN_EPS) * __ldg(&gamma[c + 0]) + __ldg(&bb[c + 0]) + xo.x;
    }
    {
        float m = g_bnsum[c + 1] * invN;
        float var = g_bnsq[c + 1] * invN - m * m;
        v.y = (h.y - m) * rsqrtf(var + BN_EPS) * __ldg(&gamma[c + 1]) + __ldg(&bb[c + 1]) + xo.y;
    }
    {
        float m = g_bnsum[c + 2] * invN;
        float var = g_bnsq[c + 2] * invN - m * m;
        v.z = (h.z - m) * rsqrtf(var + BN_EPS) * __ldg(&gamma[c + 2]) + __ldg(&bb[c + 2]) + xo.z;
    }
    {
        float m = g_bnsum[c + 3] * invN;
        float var = g_bnsq[c + 3] * invN - m * m;
        v.w = (h.w - m) * rsqrtf(var + BN_EPS) * __ldg(&gamma[c + 3]) + __ldg(&bb[c + 3]) + xo.w;
    }
    v.x = fmaxf(v.x, 0.f); v.y = fmaxf(v.y, 0.f);
    v.z = fmaxf(v.z, 0.f); v.w = fmaxf(v.w, 0.f);
    *(float4*)&g_x[idx] = v;
    store_xh(n, q, v);
}

// --- final: out = x @ W1 + b1  (K = 64, fp32) ------------------------------
__global__ void k_out(const float* __restrict__ W1,
                      const float* __restrict__ b1,
                      float* __restrict__ out) {
    extern __shared__ float sm[];
    float* ssh = sm;               // 128 x 68
    float* wsh = sm + 128 * 68;    // 64 x 64
    const int tid  = threadIdx.x;
    const int row0 = blockIdx.x * 128;

    for (int i = tid; i < 1024; i += 256)
        ((float4*)wsh)[i] = ((const float4*)W1)[i];
    for (int i = tid; i < 2048; i += 256) {
        int r = i >> 4, kq = i & 15;
        int gr = row0 + r;
        float4 v = make_float4(0.f, 0.f, 0.f, 0.f);
        if (gr < Nn) v = *(const float4*)&g_x[gr * HID + kq * 4];
        *(float4*)&ssh[r * 68 + kq * 4] = v;
    }
    __syncthreads();

    const int rg = tid >> 4;
    const int og = tid & 15;
    float4 acc[8];
    #pragma unroll
    for (int i = 0; i < 8; i++) acc[i] = make_float4(0.f, 0.f, 0.f, 0.f);

    #pragma unroll
    for (int k4 = 0; k4 < 16; k4++) {
        float4 wv0 = *(float4*)&wsh[(k4 * 4 + 0) * 64 + og * 4];
        float4 wv1 = *(float4*)&wsh[(k4 * 4 + 1) * 64 + og * 4];
        float4 wv2 = *(float4*)&wsh[(k4 * 4 + 2) * 64 + og * 4];
        float4 wv3 = *(float4*)&wsh[(k4 * 4 + 3) * 64 + og * 4];
        #pragma unroll
        for (int i = 0; i < 8; i++) {
            float4 sv = *(float4*)&ssh[(rg * 8 + i) * 68 + k4 * 4];
            fma4(acc[i], sv.x, wv0); fma4(acc[i], sv.y, wv1);
            fma4(acc[i], sv.z, wv2); fma4(acc[i], sv.w, wv3);
        }
    }

    float4 bv = __ldg((const float4*)&b1[og * 4]);
    #pragma unroll
    for (int i = 0; i < 8; i++) {
        int gr = row0 + rg * 8 + i;
        if (gr < Nn) {
            float4 v;
            v.x = acc[i].x + bv.x; v.y = acc[i].y + bv.y;
            v.z = acc[i].z + bv.z; v.w = acc[i].w + bv.w;
            *(float4*)&out[gr * HID + og * 4] = v;
        }
    }
}

// ---------------------------------------------------------------------------
extern "C" void kernel_launch(void* const* d_in, const int* in_sizes, int n_in,
                              void* d_out, int out_size) {
    const float* x     = (const float*)d_in[0];
    const int*   ei    = (const int*)  d_in[1];
    const float* W0    = (const float*)d_in[2];
    const float* b0    = (const float*)d_in[3];
    const float* convw = (const float*)d_in[4];
    const float* gamma = (const float*)d_in[5];
    const float* betab = (const float*)d_in[6];
    const float* W1    = (const float*)d_in[7];
    const float* b1    = (const float*)d_in[8];
    float* out = (float*)d_out;

    // Lazy one-time resource init (first call is the eager correctness run,
    // outside graph capture). No device memory is allocated here.
    static cudaStream_t s1 = nullptr, s2 = nullptr;
    static cudaEvent_t  evA = nullptr, evCSR = nullptr, evEnd = nullptr;
    if (s1 == nullptr) {
        cudaStreamCreateWithFlags(&s1, cudaStreamNonBlocking);
        cudaStreamCreateWithFlags(&s2, cudaStreamNonBlocking);
        cudaEventCreateWithFlags(&evA,   cudaEventDisableTiming);
        cudaEventCreateWithFlags(&evCSR, cudaEventDisableTiming);
        cudaEventCreateWithFlags(&evEnd, cudaEventDisableTiming);
    }

    const int SMEM_G64 = (128 * 68 + 64 * 64) * 4;   // 51200 B
    cudaFuncSetAttribute(k_mlp0,    cudaFuncAttributeMaxDynamicSharedMemorySize, SMEM_G64);
    cudaFuncSetAttribute(k_gemm_bn, cudaFuncAttributeMaxDynamicSharedMemorySize, SMEM_G64);
    cudaFuncSetAttribute(k_out,     cudaFuncAttributeMaxDynamicSharedMemorySize, SMEM_G64);

    const int GB = (Nn + 127) / 128;          // 782 gemm blocks
    const int EB = (Ee + 255) / 256;          // edge blocks

    // fork: s1 (dense mlp0) || s2 (CSR build)
    cudaEventRecord(evA, 0);
    cudaStreamWaitEvent(s1, evA, 0);
    cudaStreamWaitEvent(s2, evA, 0);

    k_zero   <<<(Nn + 255) / 256, 256, 0, s2>>>();
    k_count  <<<EB, 256, 0, s2>>>(ei);
    k_scanA  <<<NBLK, RPB, 0, s2>>>();
    k_scanB  <<<1, 256, 0, s2>>>();
    k_scanC  <<<NBLK, RPB, 0, s2>>>();
    k_scatter<<<EB, 256, 0, s2>>>(ei);
    cudaEventRecord(evCSR, s2);

    k_mlp0<<<GB, 256, SMEM_G64, s1>>>(x, W0, b0);

    // join: layers need both CSR and x
    cudaStreamWaitEvent(s1, evCSR, 0);

    const int SPB = (Nn * 32 + 255) / 256;    // 8 warps (rows) per block
    for (int i = 0; i < 4; i++) {
        k_spmm_csr<<<SPB, 256, 0, s1>>>();
        float beta = (float)log(0.5 / (double)(i + 1) + 1.0);
        k_gemm_bn<<<GB, 256, SMEM_G64, s1>>>(convw + i * HID * HID, beta);
        k_post<<<(Nn * 16 + 255) / 256, 256, 0, s1>>>(gamma + i * HID, betab + i * HID);
    }

    k_out<<<GB, 256, SMEM_G64, s1>>>(W1, b1, out);

    // join back to caller's stream
    cudaEventRecord(evEnd, s1);
    cudaStreamWaitEvent(0, evEnd, 0);
}

// round 9
// speedup vs baseline: 1.3418x; 1.0877x over previous
#include <cuda_runtime.h>
#include <cuda_bf16.h>
#include <cuda_fp16.h>
#include <math.h>

// ---------------------------------------------------------------------------
// GCN2 (GCNII) forward:  N=100000, E=1e6, IN=128, HID=64, OUT=64, L=4
//
// R9: dense GEMMs on tensor cores (mma.sync m16n8k16 fp16 -> fp32 accum).
//   stream fork:  [s2] CSR build   ||   [s1] mlp0 (tensor GEMM)
//   per layer: spmm (fp16 gather, fp32 accum; writes s fp32 + fp16 shadow)
//              gemm_bn (tensor GEMM + BN partial sums)
//              post (BN apply + residual + relu; refresh fp16 shadow)
//   out = x @ W1 + b1  (tensor GEMM from fp16 shadow)
// ---------------------------------------------------------------------------

#define Nn   100000
#define Ee   1000000
#define HID  64
#define BN_EPS 1e-5f

#define RPB   512
#define NBLK  ((Nn + RPB - 1) / RPB)   // 196

// ---- scratch (device globals; allocation-free) ----
__device__ __align__(16) float   g_x  [Nn * HID];
__device__ __align__(16) float   g_x0 [Nn * HID];
__device__ __align__(16) float   g_s  [Nn * HID];
__device__ __align__(16) float   g_h  [Nn * HID];
__device__ __align__(16) __half2 g_xh [Nn * 32];   // fp16 shadow of g_x
__device__ __align__(16) __half2 g_sh [Nn * 32];   // fp16 shadow of g_s
__device__ int2    g_edge[Ee];
__device__ int     g_cnt[Nn];
__device__ int     g_cur[Nn];
__device__ int     g_rowstart[Nn];
__device__ int     g_blocksum[NBLK];
__device__ int     g_blockoff[NBLK];
__device__ float   g_bnsum[HID];
__device__ float   g_bnsq [HID];

// ---------------------------------------------------------------------------
// CSR construction
// ---------------------------------------------------------------------------
__global__ void k_zero() {
    int i = blockIdx.x * blockDim.x + threadIdx.x;
    if (i < Nn) { g_cnt[i] = 0; g_cur[i] = 0; }
}

__global__ void k_count(const int* __restrict__ ei) {
    int e = blockIdx.x * blockDim.x + threadIdx.x;
    if (e < Ee) atomicAdd(&g_cnt[ei[e]], 1);
}

__global__ void k_scanA() {
    __shared__ int sh[RPB];
    int r = blockIdx.x * RPB + threadIdx.x;
    sh[threadIdx.x] = (r < Nn) ? g_cnt[r] : 0;
    __syncthreads();
    for (int off = RPB / 2; off > 0; off >>= 1) {
        if (threadIdx.x < off) sh[threadIdx.x] += sh[threadIdx.x + off];
        __syncthreads();
    }
    if (threadIdx.x == 0) g_blocksum[blockIdx.x] = sh[0];
}

__global__ void k_scanB() {
    __shared__ int sh[256];
    int tid = threadIdx.x;
    int v = (tid < NBLK) ? g_blocksum[tid] : 0;
    sh[tid] = v;
    __syncthreads();
    for (int off = 1; off < 256; off <<= 1) {
        int t = (tid >= off) ? sh[tid - off] : 0;
        __syncthreads();
        sh[tid] += t;
        __syncthreads();
    }
    if (tid < NBLK) g_blockoff[tid] = sh[tid] - v;
}

__global__ void k_scanC() {
    __shared__ int sh[RPB];
    int tid = threadIdx.x;
    int r = blockIdx.x * RPB + tid;
    int v = (r < Nn) ? g_cnt[r] : 0;
    sh[tid] = v;
    __syncthreads();
    for (int off = 1; off < RPB; off <<= 1) {
        int t = (tid >= off) ? sh[tid - off] : 0;
        __syncthreads();
        sh[tid] += t;
        __syncthreads();
    }
    if (r < Nn) g_rowstart[r] = sh[tid] - v + g_blockoff[blockIdx.x];
}

__device__ __forceinline__ float dinv_of(int d) {
    return d > 0 ? rsqrtf((float)d) : 0.0f;
}

__global__ void k_scatter(const int* __restrict__ ei) {
    int e = blockIdx.x * blockDim.x + threadIdx.x;
    if (e >= Ee) return;
    int row = ei[e];
    int col = ei[Ee + e];
    int pos = g_rowstart[row] + atomicAdd(&g_cur[row], 1);
    float w = dinv_of(g_cnt[row]) * dinv_of(g_cnt[col]);
    g_edge[pos] = make_int2(col, __float_as_int(w));
}

// ---------------------------------------------------------------------------
// SPMM (gather, CSR): one warp per row, lane owns channel pair 2l,2l+1.
//   s[row] = 0.9 * sum(w * xh[col]) + 0.1 * x0[row]; writes g_s + g_sh.
// Also zeroes BN accumulators.
// ---------------------------------------------------------------------------
__global__ void k_spmm_csr() {
    if (blockIdx.x == 0 && threadIdx.x < HID) {
        g_bnsum[threadIdx.x] = 0.0f;
        g_bnsq [threadIdx.x] = 0.0f;
    }
    int warp = (blockIdx.x * 256 + threadIdx.x) >> 5;
    int lane = threadIdx.x & 31;
    if (warp >= Nn) return;

    int start = g_rowstart[warp];
    int deg   = g_cnt[warp];

    float2 acc = make_float2(0.f, 0.f);
    #pragma unroll 4
    for (int j = 0; j < deg; j++) {
        int2 em = __ldg(&g_edge[start + j]);
        float w = __int_as_float(em.y);
        float2 v = __half22float2(__ldg(&g_xh[em.x * 32 + lane]));
        acc.x = fmaf(w, v.x, acc.x);
        acc.y = fmaf(w, v.y, acc.y);
    }
    float2 x0v = __ldg(&((const float2*)g_x0)[warp * 32 + lane]);
    float2 s;
    s.x = 0.9f * acc.x + 0.1f * x0v.x;
    s.y = 0.9f * acc.y + 0.1f * x0v.y;
    ((float2*)g_s)[warp * 32 + lane] = s;
    g_sh[warp * 32 + lane] = __floats2half2_rn(s.x, s.y);
}

// ---------------------------------------------------------------------------
// Tensor-core GEMM building blocks (mma.sync m16n8k16, fp16 in / fp32 acc)
// Block = 256 threads (8 warps), output tile 128 rows x 64 cols.
// Warp (wm = wid>>1, wn = wid&1) computes 32x32: 2 m16 x 4 n8 frags.
// ---------------------------------------------------------------------------
__device__ __forceinline__ void ldm_x4(unsigned r[4], const __half* p) {
    unsigned addr = (unsigned)__cvta_generic_to_shared(p);
    asm volatile("ldmatrix.sync.aligned.m8n8.x4.shared.b16 {%0,%1,%2,%3}, [%4];"
                 : "=r"(r[0]), "=r"(r[1]), "=r"(r[2]), "=r"(r[3]) : "r"(addr));
}
__device__ __forceinline__ void ldm_x4_t(unsigned r[4], const __half* p) {
    unsigned addr = (unsigned)__cvta_generic_to_shared(p);
    asm volatile("ldmatrix.sync.aligned.m8n8.x4.trans.shared.b16 {%0,%1,%2,%3}, [%4];"
                 : "=r"(r[0]), "=r"(r[1]), "=r"(r[2]), "=r"(r[3]) : "r"(addr));
}
__device__ __forceinline__ void mma16816(float4& d, const unsigned a[4],
                                         const unsigned b0, const unsigned b1) {
    asm volatile(
        "mma.sync.aligned.m16n8k16.row.col.f32.f16.f16.f32 "
        "{%0,%1,%2,%3}, {%4,%5,%6,%7}, {%8,%9}, {%0,%1,%2,%3};"
        : "+f"(d.x), "+f"(d.y), "+f"(d.z), "+f"(d.w)
        : "r"(a[0]), "r"(a[1]), "r"(a[2]), "r"(a[3]), "r"(b0), "r"(b1));
}

// Compute 32x32 warp tile over K (KS = K/16 steps). ash stride SA halfs,
// wsh stride 72 halfs. acc[2][4].
template <int KS, int SA>
__device__ __forceinline__ void warp_gemm(const __half* ash, const __half* wsh,
                                          int wm, int wn, int lane,
                                          float4 acc[2][4]) {
    #pragma unroll
    for (int kk = 0; kk < KS; kk++) {
        unsigned a[2][4];
        #pragma unroll
        for (int mi = 0; mi < 2; mi++)
            ldm_x4(a[mi], &ash[(wm * 32 + mi * 16 + (lane & 15)) * SA
                               + kk * 16 + (lane >> 4) * 8]);
        unsigned b[4][2];
        #pragma unroll
        for (int g = 0; g < 2; g++) {
            unsigned t[4];
            ldm_x4_t(t, &wsh[(kk * 16 + (lane & 15)) * 72
                             + wn * 32 + g * 16 + (lane >> 4) * 8]);
            b[2 * g][0] = t[0]; b[2 * g][1] = t[1];
            b[2 * g + 1][0] = t[2]; b[2 * g + 1][1] = t[3];
        }
        #pragma unroll
        for (int mi = 0; mi < 2; mi++)
            #pragma unroll
            for (int nj = 0; nj < 4; nj++)
                mma16816(acc[mi][nj], a[mi], b[nj][0], b[nj][1]);
    }
}

// --- layer 0: x = relu(X@W0 + b0); x0 = x; xh = fp16(x)  (K = 128) ---------
__global__ void k_mlp0(const float* __restrict__ X,
                       const float* __restrict__ W0,
                       const float* __restrict__ b0) {
    extern __shared__ __half smh[];
    __half* ash = smh;              // 128 x 136
    __half* wsh = smh + 128 * 136;  // 128 x 72
    const int tid = threadIdx.x, lane = tid & 31, wid = tid >> 5;
    const int row0 = blockIdx.x * 128;

    for (int i = tid; i < 4096; i += 256) {        // W0 fp32 -> fp16
        float2 w = ((const float2*)W0)[i];
        ((__half2*)wsh)[(i >> 5) * 36 + (i & 31)] = __floats2half2_rn(w.x, w.y);
    }
    for (int i = tid; i < 4096; i += 256) {        // X tile fp32 -> fp16
        int r = i >> 5, c4 = i & 31;
        int gr = row0 + r;
        float4 v = make_float4(0.f, 0.f, 0.f, 0.f);
        if (gr < Nn) v = ((const float4*)X)[gr * 32 + c4];
        __half2 h0 = __floats2half2_rn(v.x, v.y);
        __half2 h1 = __floats2half2_rn(v.z, v.w);
        uint2 p = make_uint2(*(unsigned*)&h0, *(unsigned*)&h1);
        *(uint2*)&ash[r * 136 + c4 * 4] = p;
    }
    __syncthreads();

    const int wm = wid >> 1, wn = wid & 1;
    float4 acc[2][4];
    #pragma unroll
    for (int mi = 0; mi < 2; mi++)
        #pragma unroll
        for (int nj = 0; nj < 4; nj++) acc[mi][nj] = make_float4(0.f, 0.f, 0.f, 0.f);

    warp_gemm<8, 136>(ash, wsh, wm, wn, lane, acc);

    #pragma unroll
    for (int mi = 0; mi < 2; mi++) {
        #pragma unroll
        for (int nj = 0; nj < 4; nj++) {
            int col = wn * 32 + nj * 8 + (lane & 3) * 2;
            float2 bv = *(const float2*)&b0[col];
            int r0 = row0 + wm * 32 + mi * 16 + (lane >> 2);
            int r1 = r0 + 8;
            if (r0 < Nn) {
                float2 v = make_float2(fmaxf(acc[mi][nj].x + bv.x, 0.f),
                                       fmaxf(acc[mi][nj].y + bv.y, 0.f));
                int idx = r0 * 32 + (col >> 1);
                ((float2*)g_x)[idx] = v;  ((float2*)g_x0)[idx] = v;
                g_xh[idx] = __floats2half2_rn(v.x, v.y);
            }
            if (r1 < Nn) {
                float2 v = make_float2(fmaxf(acc[mi][nj].z + bv.x, 0.f),
                                       fmaxf(acc[mi][nj].w + bv.y, 0.f));
                int idx = r1 * 32 + (col >> 1);
                ((float2*)g_x)[idx] = v;  ((float2*)g_x0)[idx] = v;
                g_xh[idx] = __floats2half2_rn(v.x, v.y);
            }
        }
    }
}

// --- mid layer: h = (1-b)*s + b*(s@Wc); BN partial sums --------------------
__global__ void k_gemm_bn(const float* __restrict__ Wc, float beta) {
    extern __shared__ __half smh[];
    __half* ash = smh;             // 128 x 72
    __half* wsh = smh + 128 * 72;  // 64 x 72
    __shared__ float bsum[HID], bsq[HID];
    const int tid = threadIdx.x, lane = tid & 31, wid = tid >> 5;
    const int row0 = blockIdx.x * 128;
    if (tid < HID) { bsum[tid] = 0.f; bsq[tid] = 0.f; }

    for (int i = tid; i < 2048; i += 256) {        // Wc fp32 -> fp16
        float2 w = ((const float2*)Wc)[i];
        ((__half2*)wsh)[(i >> 5) * 36 + (i & 31)] = __floats2half2_rn(w.x, w.y);
    }
    for (int i = tid; i < 1024; i += 256) {        // s tile (fp16 shadow)
        int r = i >> 3, c = i & 7;
        int gr = row0 + r;
        uint4 v = make_uint4(0, 0, 0, 0);
        if (gr < Nn) v = ((const uint4*)g_sh)[gr * 8 + c];
        *(uint4*)&ash[r * 72 + c * 8] = v;
    }
    __syncthreads();

    const int wm = wid >> 1, wn = wid & 1;
    float4 acc[2][4];
    #pragma unroll
    for (int mi = 0; mi < 2; mi++)
        #pragma unroll
        for (int nj = 0; nj < 4; nj++) acc[mi][nj] = make_float4(0.f, 0.f, 0.f, 0.f);

    warp_gemm<4, 72>(ash, wsh, wm, wn, lane, acc);

    const float ombeta = 1.0f - beta;
    float lsum[8], lsq[8];
    #pragma unroll
    for (int k = 0; k < 8; k++) { lsum[k] = 0.f; lsq[k] = 0.f; }

    #pragma unroll
    for (int mi = 0; mi < 2; mi++) {
        #pragma unroll
        for (int nj = 0; nj < 4; nj++) {
            int col = wn * 32 + nj * 8 + (lane & 3) * 2;
            int r0 = row0 + wm * 32 + mi * 16 + (lane >> 2);
            int r1 = r0 + 8;
            if (r0 < Nn) {
                int idx = r0 * 32 + (col >> 1);
                float2 s = ((const float2*)g_s)[idx];
                float hx = ombeta * s.x + beta * acc[mi][nj].x;
                float hy = ombeta * s.y + beta * acc[mi][nj].y;
                ((float2*)g_h)[idx] = make_float2(hx, hy);
                lsum[nj * 2] += hx;  lsum[nj * 2 + 1] += hy;
                lsq [nj * 2] += hx * hx;  lsq[nj * 2 + 1] += hy * hy;
            }
            if (r1 < Nn) {
                int idx = r1 * 32 + (col >> 1);
                float2 s = ((const float2*)g_s)[idx];
                float hx = ombeta * s.x + beta * acc[mi][nj].z;
                float hy = ombeta * s.y + beta * acc[mi][nj].w;
                ((float2*)g_h)[idx] = make_float2(hx, hy);
                lsum[nj * 2] += hx;  lsum[nj * 2 + 1] += hy;
                lsq [nj * 2] += hx * hx;  lsq[nj * 2 + 1] += hy * hy;
            }
        }
    }
    // reduce across lanes sharing (lane & 3)
    #pragma unroll
    for (int off = 16; off >= 4; off >>= 1) {
        #pragma unroll
        for (int k = 0; k < 8; k++) {
            lsum[k] += __shfl_xor_sync(0xffffffffu, lsum[k], off);
            lsq [k] += __shfl_xor_sync(0xffffffffu, lsq [k], off);
        }
    }
    if ((lane >> 2) == 0) {
        #pragma unroll
        for (int nj = 0; nj < 4; nj++) {
            #pragma unroll
            for (int p = 0; p < 2; p++) {
                int col = wn * 32 + nj * 8 + (lane & 3) * 2 + p;
                atomicAdd(&bsum[col], lsum[nj * 2 + p]);
                atomicAdd(&bsq [col], lsq [nj * 2 + p]);
            }
        }
    }
    __syncthreads();
    if (tid < HID) {
        atomicAdd(&g_bnsum[tid], bsum[tid]);
        atomicAdd(&g_bnsq [tid], bsq [tid]);
    }
}

// --- BN apply + residual + relu -> g_x, g_xh -------------------------------
__global__ void k_post(const float* __restrict__ gamma,
                       const float* __restrict__ bb) {
    int t = blockIdx.x * 256 + threadIdx.x;
    int n = t >> 4, q = t & 15;
    if (n >= Nn) return;
    int c = q * 4;
    int idx = n * HID + c;
    const float invN = 1.0f / (float)Nn;

    float4 h  = *(float4*)&g_h[idx];
    float4 xo = *(float4*)&g_x[idx];
    float4 v;
    {
        float m = g_bnsum[c + 0] * invN;
        float var = g_bnsq[c + 0] * invN - m * m;
        v.x = (h.x - m) * rsqrtf(var + BN_EPS) * __ldg(&gamma[c + 0]) + __ldg(&bb[c + 0]) + xo.x;
    }
    {
        float m = g_bnsum[c + 1] * invN;
        float var = g_bnsq[c + 1] * invN - m * m;
        v.y = (h.y - m) * rsqrtf(var + BN_EPS) * __ldg(&gamma[c + 1]) + __ldg(&bb[c + 1]) + xo.y;
    }
    {
        float m = g_bnsum[c + 2] * invN;
        float var = g_bnsq[c + 2] * invN - m * m;
        v.z = (h.z - m) * rsqrtf(var + BN_EPS) * __ldg(&gamma[c + 2]) + __ldg(&bb[c + 2]) + xo.z;
    }
    {
        float m = g_bnsum[c + 3] * invN;
        float var = g_bnsq[c + 3] * invN - m * m;
        v.w = (h.w - m) * rsqrtf(var + BN_EPS) * __ldg(&gamma[c + 3]) + __ldg(&bb[c + 3]) + xo.w;
    }
    v.x = fmaxf(v.x, 0.f); v.y = fmaxf(v.y, 0.f);
    v.z = fmaxf(v.z, 0.f); v.w = fmaxf(v.w, 0.f);
    *(float4*)&g_x[idx] = v;
    __half2 h0 = __floats2half2_rn(v.x, v.y);
    __half2 h1 = __floats2half2_rn(v.z, v.w);
    uint2 p = make_uint2(*(unsigned*)&h0, *(unsigned*)&h1);
    *(uint2*)&g_xh[n * 32 + q * 2] = p;
}

// --- final: out = x @ W1 + b1  (K = 64, from fp16 shadow) ------------------
__global__ void k_out(const float* __restrict__ W1,
                      const float* __restrict__ b1,
                      float* __restrict__ out) {
    extern __shared__ __half smh[];
    __half* ash = smh;             // 128 x 72
    __half* wsh = smh + 128 * 72;  // 64 x 72
    const int tid = threadIdx.x, lane = tid & 31, wid = tid >> 5;
    const int row0 = blockIdx.x * 128;

    for (int i = tid; i < 2048; i += 256) {
        float2 w = ((const float2*)W1)[i];
        ((__half2*)wsh)[(i >> 5) * 36 + (i & 31)] = __floats2half2_rn(w.x, w.y);
    }
    for (int i = tid; i < 1024; i += 256) {
        int r = i >> 3, c = i & 7;
        int gr = row0 + r;
        uint4 v = make_uint4(0, 0, 0, 0);
        if (gr < Nn) v = ((const uint4*)g_xh)[gr * 8 + c];
        *(uint4*)&ash[r * 72 + c * 8] = v;
    }
    __syncthreads();

    const int wm = wid >> 1, wn = wid & 1;
    float4 acc[2][4];
    #pragma unroll
    for (int mi = 0; mi < 2; mi++)
        #pragma unroll
        for (int nj = 0; nj < 4; nj++) acc[mi][nj] = make_float4(0.f, 0.f, 0.f, 0.f);

    warp_gemm<4, 72>(ash, wsh, wm, wn, lane, acc);

    #pragma unroll
    for (int mi = 0; mi < 2; mi++) {
        #pragma unroll
        for (int nj = 0; nj < 4; nj++) {
            int col = wn * 32 + nj * 8 + (lane & 3) * 2;
            float2 bv = *(const float2*)&b1[col];
            int r0 = row0 + wm * 32 + mi * 16 + (lane >> 2);
            int r1 = r0 + 8;
            if (r0 < Nn)
                ((float2*)out)[r0 * 32 + (col >> 1)] =
                    make_float2(acc[mi][nj].x + bv.x, acc[mi][nj].y + bv.y);
            if (r1 < Nn)
                ((float2*)out)[r1 * 32 + (col >> 1)] =
                    make_float2(acc[mi][nj].z + bv.x, acc[mi][nj].w + bv.y);
        }
    }
}

// ---------------------------------------------------------------------------
extern "C" void kernel_launch(void* const* d_in, const int* in_sizes, int n_in,
                              void* d_out, int out_size) {
    const float* x     = (const float*)d_in[0];
    const int*   ei    = (const int*)  d_in[1];
    const float* W0    = (const float*)d_in[2];
    const float* b0    = (const float*)d_in[3];
    const float* convw = (const float*)d_in[4];
    const float* gamma = (const float*)d_in[5];
    const float* betab = (const float*)d_in[6];
    const float* W1    = (const float*)d_in[7];
    const float* b1    = (const float*)d_in[8];
    float* out = (float*)d_out;

    static cudaStream_t s1 = nullptr, s2 = nullptr;
    static cudaEvent_t  evA = nullptr, evCSR = nullptr, evEnd = nullptr;
    if (s1 == nullptr) {
        cudaStreamCreateWithFlags(&s1, cudaStreamNonBlocking);
        cudaStreamCreateWithFlags(&s2, cudaStreamNonBlocking);
        cudaEventCreateWithFlags(&evA,   cudaEventDisableTiming);
        cudaEventCreateWithFlags(&evCSR, cudaEventDisableTiming);
        cudaEventCreateWithFlags(&evEnd, cudaEventDisableTiming);
    }

    const int SMEM_MLP0 = (128 * 136 + 128 * 72) * 2;   // 53248 B
    const int SMEM_G64  = (128 * 72  + 64  * 72) * 2;   // 27648 B
    cudaFuncSetAttribute(k_mlp0,    cudaFuncAttributeMaxDynamicSharedMemorySize, SMEM_MLP0);
    cudaFuncSetAttribute(k_gemm_bn, cudaFuncAttributeMaxDynamicSharedMemorySize, SMEM_G64);
    cudaFuncSetAttribute(k_out,     cudaFuncAttributeMaxDynamicSharedMemorySize, SMEM_G64);

    const int GB = (Nn + 127) / 128;          // 782
    const int EB = (Ee + 255) / 256;

    cudaEventRecord(evA, 0);
    cudaStreamWaitEvent(s1, evA, 0);
    cudaStreamWaitEvent(s2, evA, 0);

    k_zero   <<<(Nn + 255) / 256, 256, 0, s2>>>();
    k_count  <<<EB, 256, 0, s2>>>(ei);
    k_scanA  <<<NBLK, RPB, 0, s2>>>();
    k_scanB  <<<1, 256, 0, s2>>>();
    k_scanC  <<<NBLK, RPB, 0, s2>>>();
    k_scatter<<<EB, 256, 0, s2>>>(ei);
    cudaEventRecord(evCSR, s2);

    k_mlp0<<<GB, 256, SMEM_MLP0, s1>>>(x, W0, b0);

    cudaStreamWaitEvent(s1, evCSR, 0);

    const int SPB = (Nn * 32 + 255) / 256;
    for (int i = 0; i < 4; i++) {
        k_spmm_csr<<<SPB, 256, 0, s1>>>();
        float beta = (float)log(0.5 / (double)(i + 1) + 1.0);
        k_gemm_bn<<<GB, 256, SMEM_G64, s1>>>(convw + i * HID * HID, beta);
        k_post<<<(Nn * 16 + 255) / 256, 256, 0, s1>>>(gamma + i * HID, betab + i * HID);
    }

    k_out<<<GB, 256, SMEM_G64, s1>>>(W1, b1, out);

    cudaEventRecord(evEnd, s1);
    cudaStreamWaitEvent(0, evEnd, 0);
}